// round 1
// baseline (speedup 1.0000x reference)
#include <cuda_runtime.h>
#include <cuda_bf16.h>

// GriddingDistance forward: trilinear scatter of two point clouds into two
// B x R x R x R occupancy-weight grids (concatenated in d_out: pred first, gt second).
//
// inputs (metadata order):
//   d_in[0]: pred_cloud  float32 (B, N1, 3)
//   d_in[1]: gt_cloud    float32 (B, N2, 3)
//   d_in[2]: scale       (== R; not read — R derived from out_size)
// output: float32, 2 * B * R^3 elements.

#ifndef GRID_B
#define GRID_B 16   // batch size for this problem instance
#endif

__global__ void gridding_scatter_kernel(
    const float* __restrict__ pred,
    const float* __restrict__ gt,
    float* __restrict__ out,
    int nPred, int nGt,          // total points per cloud (B*N)
    int npbPred, int npbGt,      // points per batch
    int R,
    long long cellsPerBatch,     // R^3
    long long cloudOffset)       // B * R^3 (offset of gt grid)
{
    int t = blockIdx.x * blockDim.x + threadIdx.x;

    const float* __restrict__ src;
    float* __restrict__ dst;
    int p, npb;
    if (t < nPred) {
        src = pred; dst = out; p = t; npb = npbPred;
    } else {
        p = t - nPred;
        if (p >= nGt) return;
        src = gt; dst = out + cloudOffset; npb = npbGt;
    }

    // load point (coalesced within warp: 3 contiguous 128B segments per warp)
    float cx = src[3 * p + 0];
    float cy = src[3 * p + 1];
    float cz = src[3 * p + 2];

    float Rf = (float)R;
    // faithful to reference: p = c/scale; v = (p + 0.5) * R   (scale == R)
    float vx = (cx / Rf + 0.5f) * Rf;
    float vy = (cy / Rf + 0.5f) * Rf;
    float vz = (cz / Rf + 0.5f) * Rf;

    float flx = floorf(vx), fly = floorf(vy), flz = floorf(vz);
    int ix = (int)flx, iy = (int)fly, iz = (int)flz;
    float fx = vx - flx, fy = vy - fly, fz = vz - flz;

    float wx0 = 1.0f - fx, wx1 = fx;
    float wy0 = 1.0f - fy, wy1 = fy;
    float wz0 = 1.0f - fz, wz1 = fz;

    long long base = (long long)(p / npb) * cellsPerBatch;

    // Fast path: whole 2x2x2 cell interior (true for all points of this dataset).
    if (ix >= 0 && iy >= 0 && iz >= 0 && ix + 1 < R && iy + 1 < R && iz + 1 < R) {
        long long i000 = base + ((long long)ix * R + iy) * R + iz;
        long long strY = R;
        long long strX = (long long)R * R;
        // 8 REDG.F32 (atomicAdd with unused return)
        atomicAdd(&dst[i000],                 wx0 * wy0 * wz0);
        atomicAdd(&dst[i000 + 1],             wx0 * wy0 * wz1);
        atomicAdd(&dst[i000 + strY],          wx0 * wy1 * wz0);
        atomicAdd(&dst[i000 + strY + 1],      wx0 * wy1 * wz1);
        atomicAdd(&dst[i000 + strX],          wx1 * wy0 * wz0);
        atomicAdd(&dst[i000 + strX + 1],      wx1 * wy0 * wz1);
        atomicAdd(&dst[i000 + strX + strY],   wx1 * wy1 * wz0);
        atomicAdd(&dst[i000 + strX + strY + 1], wx1 * wy1 * wz1);
    } else {
        // Generic path: per-corner validity (reference zeroes invalid-corner weight,
        // i.e. contributes nothing -> skip the add).
        float wxa[2] = {wx0, wx1};
        float wya[2] = {wy0, wy1};
        float wza[2] = {wz0, wz1};
        #pragma unroll
        for (int dx = 0; dx < 2; dx++) {
            int x = ix + dx;
            if (x < 0 || x >= R) continue;
            #pragma unroll
            for (int dy = 0; dy < 2; dy++) {
                int y = iy + dy;
                if (y < 0 || y >= R) continue;
                #pragma unroll
                for (int dz = 0; dz < 2; dz++) {
                    int z = iz + dz;
                    if (z < 0 || z >= R) continue;
                    long long idx = base + ((long long)x * R + y) * R + z;
                    atomicAdd(&dst[idx], wxa[dx] * wya[dy] * wza[dz]);
                }
            }
        }
    }
}

static inline int icbrt(long long v) {
    int r = (int)llroundf(cbrtf((float)v));
    // fix up float error
    while ((long long)(r + 1) * (r + 1) * (r + 1) <= v) r++;
    while ((long long)r * r * r > v) r--;
    return r;
}

extern "C" void kernel_launch(void* const* d_in, const int* in_sizes, int n_in,
                              void* d_out, int out_size)
{
    const float* pred = (const float*)d_in[0];
    const float* gt   = (const float*)d_in[1];
    float* out = (float*)d_out;

    int nPred = in_sizes[0] / 3;          // B * N1
    int nGt   = in_sizes[1] / 3;          // B * N2
    int B = GRID_B;
    long long cellsPerCloud = (long long)out_size / 2;       // B * R^3
    long long cellsPerBatch = cellsPerCloud / B;             // R^3
    int R = icbrt(cellsPerBatch);

    int npbPred = nPred / B;
    int npbGt   = nGt / B;

    // zero the output grids
    cudaMemsetAsync(d_out, 0, (size_t)out_size * sizeof(float), 0);

    int total = nPred + nGt;
    int threads = 256;
    int blocks = (total + threads - 1) / threads;
    gridding_scatter_kernel<<<blocks, threads>>>(
        pred, gt, out, nPred, nGt, npbPred, npbGt,
        R, cellsPerBatch, cellsPerCloud);
}

// round 2
// speedup vs baseline: 1.0126x; 1.0126x over previous
#include <cuda_runtime.h>
#include <cuda_bf16.h>

// GriddingDistance forward: trilinear scatter of two point clouds into two
// B x R x R x R occupancy-weight grids (concatenated in d_out: pred first, gt second).
//
// R2: 4 points/thread via float4 loads (MLP), z-pair vectorized red.global.add.v2.f32,
//     pred/gt as two sequential launches for L2 locality.

#ifndef GRID_B
#define GRID_B 16   // batch size for this problem instance
#endif

__device__ __forceinline__ void red_add_v2(float* p, float a, float b) {
    asm volatile("red.global.add.v2.f32 [%0], {%1, %2};"
                 :: "l"(p), "f"(a), "f"(b) : "memory");
}
__device__ __forceinline__ void red_add(float* p, float a) {
    atomicAdd(p, a);   // REDG.F32 (return unused)
}

__device__ __forceinline__ void scatter_point(
    float cx, float cy, float cz,
    float* __restrict__ dst, long long base,
    int R, float Rf, float invR, bool evenOK)
{
    float vx = (cx * invR + 0.5f) * Rf;
    float vy = (cy * invR + 0.5f) * Rf;
    float vz = (cz * invR + 0.5f) * Rf;

    float flx = floorf(vx), fly = floorf(vy), flz = floorf(vz);
    int ix = (int)flx, iy = (int)fly, iz = (int)flz;
    float fx = vx - flx, fy = vy - fly, fz = vz - flz;

    float wx0 = 1.0f - fx, wx1 = fx;
    float wy0 = 1.0f - fy, wy1 = fy;
    float wz0 = 1.0f - fz, wz1 = fz;

    long long sY = R;
    long long sX = (long long)R * R;

    if (ix >= 0 && iy >= 0 && iz >= 0 && ix + 1 < R && iy + 1 < R && iz + 1 < R) {
        long long i000 = base + ((long long)ix * R + iy) * R + iz;
        float* g = dst + i000;
        if (evenOK && ((i000 & 1LL) == 0)) {
            // 8B-aligned z-pairs: 4 vector reductions instead of 8 scalar
            red_add_v2(g,           wx0 * wy0 * wz0, wx0 * wy0 * wz1);
            red_add_v2(g + sY,      wx0 * wy1 * wz0, wx0 * wy1 * wz1);
            red_add_v2(g + sX,      wx1 * wy0 * wz0, wx1 * wy0 * wz1);
            red_add_v2(g + sX + sY, wx1 * wy1 * wz0, wx1 * wy1 * wz1);
        } else {
            red_add(g,               wx0 * wy0 * wz0);
            red_add(g + 1,           wx0 * wy0 * wz1);
            red_add(g + sY,          wx0 * wy1 * wz0);
            red_add(g + sY + 1,      wx0 * wy1 * wz1);
            red_add(g + sX,          wx1 * wy0 * wz0);
            red_add(g + sX + 1,      wx1 * wy0 * wz1);
            red_add(g + sX + sY,     wx1 * wy1 * wz0);
            red_add(g + sX + sY + 1, wx1 * wy1 * wz1);
        }
    } else {
        // Boundary path: per-corner validity (reference zeroes invalid-corner weight).
        float wxa[2] = {wx0, wx1};
        float wya[2] = {wy0, wy1};
        float wza[2] = {wz0, wz1};
        #pragma unroll
        for (int dx = 0; dx < 2; dx++) {
            int x = ix + dx;
            if (x < 0 || x >= R) continue;
            #pragma unroll
            for (int dy = 0; dy < 2; dy++) {
                int y = iy + dy;
                if (y < 0 || y >= R) continue;
                #pragma unroll
                for (int dz = 0; dz < 2; dz++) {
                    int z = iz + dz;
                    if (z < 0 || z >= R) continue;
                    long long idx = base + ((long long)x * R + y) * R + z;
                    red_add(dst + idx, wxa[dx] * wya[dy] * wza[dz]);
                }
            }
        }
    }
}

__global__ void __launch_bounds__(256)
gridding_scatter4_kernel(
    const float* __restrict__ cloud,
    float* __restrict__ dst,
    int nPts,                    // total points (B*N)
    int npb,                     // points per batch
    int R, float Rf, float invR,
    long long cellsPerBatch)     // R^3
{
    int t = blockIdx.x * blockDim.x + threadIdx.x;
    int p0 = t * 4;
    if (p0 >= nPts) return;

    bool evenOK = ((R & 1) == 0);

    if (p0 + 4 <= nPts) {
        // 12 contiguous floats = 4 points, 3x LDG.128 (16B-aligned: t*48 bytes)
        const float4* c4 = (const float4*)cloud;
        float4 a = c4[3 * t + 0];
        float4 b = c4[3 * t + 1];
        float4 c = c4[3 * t + 2];

        float px[4] = {a.x, a.w, b.z, c.y};
        float py[4] = {a.y, b.x, b.w, c.z};
        float pz[4] = {a.z, b.y, c.x, c.w};

        #pragma unroll
        for (int j = 0; j < 4; j++) {
            int p = p0 + j;
            long long base = (long long)(p / npb) * cellsPerBatch;
            scatter_point(px[j], py[j], pz[j], dst, base, R, Rf, invR, evenOK);
        }
    } else {
        for (int p = p0; p < nPts; p++) {
            long long base = (long long)(p / npb) * cellsPerBatch;
            scatter_point(cloud[3 * p + 0], cloud[3 * p + 1], cloud[3 * p + 2],
                          dst, base, R, Rf, invR, evenOK);
        }
    }
}

static inline int icbrt(long long v) {
    int r = (int)llroundf(cbrtf((float)v));
    while ((long long)(r + 1) * (r + 1) * (r + 1) <= v) r++;
    while ((long long)r * r * r > v) r--;
    return r;
}

extern "C" void kernel_launch(void* const* d_in, const int* in_sizes, int n_in,
                              void* d_out, int out_size)
{
    const float* pred = (const float*)d_in[0];
    const float* gt   = (const float*)d_in[1];
    float* out = (float*)d_out;

    int nPred = in_sizes[0] / 3;          // B * N1
    int nGt   = in_sizes[1] / 3;          // B * N2
    int B = GRID_B;
    long long cellsPerCloud = (long long)out_size / 2;       // B * R^3
    long long cellsPerBatch = cellsPerCloud / B;             // R^3
    int R = icbrt(cellsPerBatch);
    float Rf = (float)R;
    float invR = 1.0f / Rf;

    int npbPred = nPred / B;
    int npbGt   = nGt / B;

    cudaMemsetAsync(d_out, 0, (size_t)out_size * sizeof(float), 0);

    int threads = 256;
    {
        int nThr = (nPred + 3) / 4;
        int blocks = (nThr + threads - 1) / threads;
        gridding_scatter4_kernel<<<blocks, threads>>>(
            pred, out, nPred, npbPred, R, Rf, invR, cellsPerBatch);
    }
    {
        int nThr = (nGt + 3) / 4;
        int blocks = (nThr + threads - 1) / threads;
        gridding_scatter4_kernel<<<blocks, threads>>>(
            gt, out + cellsPerCloud, nGt, npbGt, R, Rf, invR, cellsPerBatch);
    }
}